// round 8
// baseline (speedup 1.0000x reference)
#include <cuda_runtime.h>
#include <cuda_bf16.h>
#include <math.h>
#include <stdint.h>

#define BB   256
#define EMB  512
#define CLS  20000
#define NTL  157              // N tiles

#define MT   128
#define NT   128
#define KC   32
#define NCH  (EMB / KC)       // 16 k-chunks
#define STG  49152            // stage bytes: Ahi 8K | Alo 8K | Bf32 16K | Bhi 8K | Blo 8K

// ---------------- device scratch ----------------
__device__ __align__(16) __nv_bfloat16 g_Ahi[2 * BB * EMB];
__device__ __align__(16) __nv_bfloat16 g_Alo[2 * BB * EMB];
__device__ float g_n2p[8 * CLS];      // colnorm partials
__device__ float g_inv[CLS];          // 1/||W_col||
__device__ float g_xlen[BB];
__device__ float g_pmax[BB * NTL];    // per-(row,tile) softmax partials
__device__ float g_psum[BB * NTL];
__device__ int   g_pbi [BB * NTL];
__device__ float g_inter_sum;
__device__ float g_row_ce[BB];
__device__ int   g_row_correct[BB];

// ---------------- PTX helpers ----------------
__device__ __forceinline__ uint32_t s2u(const void* p) {
    return (uint32_t)__cvta_generic_to_shared(p);
}
__device__ __forceinline__ void cp_async16(uint32_t dst, const void* src, int szbytes) {
    asm volatile("cp.async.cg.shared.global [%0], [%1], 16, %2;"
                 :: "r"(dst), "l"(src), "r"(szbytes));
}
#define CP_COMMIT() asm volatile("cp.async.commit_group;" ::: "memory")
#define CP_WAIT(n)  asm volatile("cp.async.wait_group %0;" :: "n"(n) : "memory")

__device__ __forceinline__ void ldm_x4(uint32_t* r, uint32_t addr) {
    asm volatile("ldmatrix.sync.aligned.m8n8.x4.shared.b16 {%0,%1,%2,%3}, [%4];"
                 : "=r"(r[0]), "=r"(r[1]), "=r"(r[2]), "=r"(r[3]) : "r"(addr));
}
__device__ __forceinline__ void ldm_x4_t(uint32_t* r, uint32_t addr) {
    asm volatile("ldmatrix.sync.aligned.m8n8.x4.trans.shared.b16 {%0,%1,%2,%3}, [%4];"
                 : "=r"(r[0]), "=r"(r[1]), "=r"(r[2]), "=r"(r[3]) : "r"(addr));
}
__device__ __forceinline__ void mma16816(float* c, const uint32_t* a,
                                         uint32_t b0, uint32_t b1) {
    asm volatile("mma.sync.aligned.m16n8k16.row.col.f32.bf16.bf16.f32 "
                 "{%0,%1,%2,%3}, {%4,%5,%6,%7}, {%8,%9}, {%0,%1,%2,%3};"
                 : "+f"(c[0]), "+f"(c[1]), "+f"(c[2]), "+f"(c[3])
                 : "r"(a[0]), "r"(a[1]), "r"(a[2]), "r"(a[3]), "r"(b0), "r"(b1));
}

// ---------------- colnorm partials (atomic-free) ----------------
__global__ void k_colnorm(const float* __restrict__ W) {
    int j = blockIdx.x * blockDim.x + threadIdx.x;
    if (blockIdx.x == 0 && blockIdx.y == 0 && threadIdx.x == 0) g_inter_sum = 0.0f;
    if (j >= CLS) return;
    int i0 = blockIdx.y * 64;
    float s = 0.0f;
#pragma unroll 8
    for (int i = 0; i < 64; i++) {
        float v = W[(size_t)(i0 + i) * CLS + j];
        s += v * v;
    }
    g_n2p[blockIdx.y * CLS + j] = s;
}

__global__ void k_nred() {
    int j = blockIdx.x * blockDim.x + threadIdx.x;
    if (j >= CLS) return;
    float s = 0.0f;
#pragma unroll
    for (int p = 0; p < 8; p++) s += g_n2p[p * CLS + j];
    g_inv[j] = rsqrtf(s);
}

// 512 blocks: b<BB: emb split + xlen; else Wy = W[:,t]*inv split
__global__ void k_prep(const float* __restrict__ emb,
                       const float* __restrict__ W,
                       const int* __restrict__ y) {
    int b = blockIdx.x;
    int tid = threadIdx.x;   // 128
    if (b < BB) {
        float s = 0.0f;
        for (int k = tid; k < EMB; k += 128) {
            float v = emb[b * EMB + k];
            s += v * v;
            __nv_bfloat16 h = __float2bfloat16(v);
            g_Ahi[b * EMB + k] = h;
            g_Alo[b * EMB + k] = __float2bfloat16(v - __bfloat162float(h));
        }
        __shared__ float sm[128];
        sm[tid] = s;
        __syncthreads();
        for (int o = 64; o > 0; o >>= 1) {
            if (tid < o) sm[tid] += sm[tid + o];
            __syncthreads();
        }
        if (tid == 0) g_xlen[b] = sqrtf(sm[0]);
    } else {
        int t = y[b - BB];
        float inv = g_inv[t];
        for (int k = tid; k < EMB; k += 128) {
            float v = W[(size_t)k * CLS + t] * inv;
            __nv_bfloat16 h = __float2bfloat16(v);
            g_Ahi[b * EMB + k] = h;
            g_Alo[b * EMB + k] = __float2bfloat16(v - __bfloat162float(h));
        }
    }
}

// ---------------- fused GEMM: in-kernel W normalize+split, 3-stage pipeline ----------------
__global__ __launch_bounds__(512, 1) void k_gemm(const float* __restrict__ W,
                                                 const int* __restrict__ y,
                                                 float* __restrict__ logits) {
    extern __shared__ __align__(16) char dsm[];
    __shared__ float sInv[128];
    __shared__ float spm[512];
    __shared__ float sse[512];
    __shared__ int   sbx[512];
    uint32_t sb = s2u(dsm);

    int tid  = threadIdx.x;
    int wid  = tid >> 5, lane = tid & 31;
    int wm   = wid & 3, wn = wid >> 2;
    int bn   = blockIdx.x, bm = blockIdx.y;
    int rowBase = bm * MT, colBase = bn * NT;

    if (tid < 128) {
        int j = colBase + tid;
        sInv[tid] = (j < CLS) ? g_inv[j] : 1.0f;
    }

    float acc[2][4][4];
#pragma unroll
    for (int mi = 0; mi < 2; mi++)
#pragma unroll
        for (int ni = 0; ni < 4; ni++)
#pragma unroll
            for (int k = 0; k < 4; k++) acc[mi][ni][k] = 0.0f;

    // A (pre-split bf16) + B (raw fp32) loads into stage s
    auto load_tiles = [&](int kc, int s) {
        uint32_t base = sb + s * STG;
        {
            int r = tid >> 2, c8 = tid & 3;   // A: 128 rows x 4 16B-chunks
            uint32_t soff = (uint32_t)(r * 64 + ((c8 ^ ((r >> 1) & 3)) << 4));
            size_t go = (size_t)(rowBase + r) * EMB + kc + c8 * 8;
            cp_async16(base + soff,        g_Ahi + go, 16);
            cp_async16(base + 8192 + soff, g_Alo + go, 16);
        }
        {
            int k = tid >> 4, c8 = tid & 15;  // B fp32: 32 rows x 16 chunks of 8 floats
            int col = colBase + c8 * 8;
            int ok = (col < CLS) ? 16 : 0;
            const float* src = W + (size_t)(kc + k) * CLS + (ok ? col : colBase);
            uint32_t dst = base + 16384 + (uint32_t)(k * 512 + c8 * 32);
            cp_async16(dst,      src,     ok);
            cp_async16(dst + 16, src + 4, ok);
        }
    };

    // normalize + bf16 hi/lo split: fp32 buf -> Bhi/Blo (swizzled), stage s
    auto convert = [&](int s) {
        int k = tid >> 4, c16 = tid & 15;
        const float* f32 = (const float*)(dsm + s * STG + 16384) + k * 128 + c16 * 8;
        float4 v0 = *(const float4*)f32;
        float4 v1 = *(const float4*)(f32 + 4);
        float f[8] = {v0.x, v0.y, v0.z, v0.w, v1.x, v1.y, v1.z, v1.w};
        alignas(16) __nv_bfloat16 hb[8];
        alignas(16) __nv_bfloat16 lb[8];
#pragma unroll
        for (int q = 0; q < 8; q++) {
            float v = f[q] * sInv[c16 * 8 + q];
            __nv_bfloat16 h = __float2bfloat16(v);
            hb[q] = h;
            lb[q] = __float2bfloat16(v - __bfloat162float(h));
        }
        uint32_t off = (uint32_t)(k * 256 + ((c16 ^ (k & 7)) << 4));
        *(uint4*)(dsm + s * STG + 32768 + off) = *(const uint4*)hb;
        *(uint4*)(dsm + s * STG + 40960 + off) = *(const uint4*)lb;
    };

    load_tiles(0, 0); CP_COMMIT();
    load_tiles(KC, 1); CP_COMMIT();

    int ln15 = lane & 15, half = lane >> 4;

    for (int ch = 0; ch < NCH; ch++) {
        if (ch + 1 < NCH) { CP_WAIT(1); } else { CP_WAIT(0); }
        __syncthreads();
        int s = ch % 3;
        convert(s);
        if (ch + 2 < NCH) { load_tiles((ch + 2) * KC, (ch + 2) % 3); CP_COMMIT(); }
        __syncthreads();

        uint32_t base = sb + s * STG;
#pragma unroll
        for (int ks = 0; ks < 2; ks++) {
            uint32_t ah[2][4], al[2][4], bh[2][4], bl[2][4];
#pragma unroll
            for (int mi = 0; mi < 2; mi++) {
                int r = wm * 32 + mi * 16 + ln15;
                int c8 = ks * 2 + half;
                uint32_t off = (uint32_t)(r * 64 + ((c8 ^ ((r >> 1) & 3)) << 4));
                ldm_x4(ah[mi], base + off);
                ldm_x4(al[mi], base + 8192 + off);
            }
#pragma unroll
            for (int nb = 0; nb < 2; nb++) {
                int r = ks * 16 + ln15;
                int c16 = wn * 4 + nb * 2 + half;
                uint32_t off = (uint32_t)(r * 256 + ((c16 ^ (r & 7)) << 4));
                ldm_x4_t(bh[nb], base + 32768 + off);
                ldm_x4_t(bl[nb], base + 40960 + off);
            }
#pragma unroll
            for (int mi = 0; mi < 2; mi++)
#pragma unroll
                for (int ni = 0; ni < 4; ni++)
                    mma16816(acc[mi][ni], ah[mi],
                             bh[ni >> 1][(ni & 1) * 2], bh[ni >> 1][(ni & 1) * 2 + 1]);
#pragma unroll
            for (int mi = 0; mi < 2; mi++)
#pragma unroll
                for (int ni = 0; ni < 4; ni++)
                    mma16816(acc[mi][ni], al[mi],
                             bh[ni >> 1][(ni & 1) * 2], bh[ni >> 1][(ni & 1) * 2 + 1]);
#pragma unroll
            for (int mi = 0; mi < 2; mi++)
#pragma unroll
                for (int ni = 0; ni < 4; ni++)
                    mma16816(acc[mi][ni], ah[mi],
                             bl[ni >> 1][(ni & 1) * 2], bl[ni >> 1][(ni & 1) * 2 + 1]);
        }
        __syncthreads();
    }

    // ---------------- epilogue ----------------
    if (bm < 2) {
        float* epi = (float*)dsm;   // [128][129] raw acc
#pragma unroll
        for (int mi = 0; mi < 2; mi++)
#pragma unroll
            for (int ni = 0; ni < 4; ni++)
#pragma unroll
                for (int k = 0; k < 4; k++) {
                    int row = wm * 32 + mi * 16 + (k >> 1) * 8 + (lane >> 2);
                    int col = wn * 32 + ni * 8 + (lane & 3) * 2 + (k & 1);
                    epi[row * 129 + col] = acc[mi][ni][k];
                }
        __syncthreads();
        // coalesced logits store
        {
            int r0 = tid >> 7, c0 = tid & 127;
            int j = colBase + c0;
            if (j < CLS) {
#pragma unroll 8
                for (int rr = 0; rr < 32; rr++) {
                    int mm = rr * 4 + r0;
                    int b = rowBase + mm;
                    float xl = g_xlen[b];
                    float v = epi[mm * 129 + c0];
                    float cv = fminf(fmaxf(v / xl, -1.0f), 1.0f);
                    logits[(size_t)b * CLS + j] = cv * xl;
                }
            }
        }
        // per-(row, tile) softmax/argmax partials
        {
            int row = tid & 127, q = tid >> 7;
            float xl = g_xlen[rowBase + row];
            int cb = q * 32;
            bool valid = (colBase + cb) < CLS;
            float bv = -3.0e38f, se = 0.0f;
            int bi = 0x7fffffff;
            if (valid) {
#pragma unroll 8
                for (int c = 0; c < 32; c++) {
                    float v = epi[row * 129 + cb + c];
                    float cv = fminf(fmaxf(v / xl, -1.0f), 1.0f) * xl;
                    if (cv > bv) { bv = cv; bi = colBase + cb + c; }
                }
#pragma unroll 8
                for (int c = 0; c < 32; c++) {
                    float v = epi[row * 129 + cb + c];
                    float cv = fminf(fmaxf(v / xl, -1.0f), 1.0f) * xl;
                    se += __expf(cv - bv);
                }
            }
            spm[q * 128 + row] = bv;
            sse[q * 128 + row] = se;
            sbx[q * 128 + row] = bi;
        }
        __syncthreads();
        if (tid < 128) {
            float M = -3.0e38f, sum = 0.0f;
            int bi = 0x7fffffff;
#pragma unroll
            for (int q = 0; q < 4; q++) {
                float m = spm[q * 128 + tid];
                if (m > M) { M = m; bi = sbx[q * 128 + tid]; }
            }
#pragma unroll
            for (int q = 0; q < 4; q++)
                sum += sse[q * 128 + tid] * __expf(spm[q * 128 + tid] - M);
            int b = rowBase + tid;
            g_pmax[b * NTL + bn] = M;
            g_psum[b * NTL + bn] = sum;
            g_pbi [b * NTL + bn] = bi;
        }
    } else {
        float il = 0.0f;
#pragma unroll
        for (int mi = 0; mi < 2; mi++) {
#pragma unroll
            for (int k2 = 0; k2 < 2; k2++) {
                int row = wm * 32 + mi * 16 + k2 * 8 + (lane >> 2);
                int b = rowBase + row - BB;
                int t = y[b];
#pragma unroll
                for (int ni = 0; ni < 4; ni++)
#pragma unroll
                    for (int p = 0; p < 2; p++) {
                        int j = colBase + wn * 32 + ni * 8 + (lane & 3) * 2 + p;
                        if (j < CLS && j != t) {
                            float c = acc[mi][ni][k2 * 2 + p];
                            float d2 = fmaxf(2.0f - 2.0f * c, 0.0f);
                            il += 1.0f / d2;
                        }
                    }
            }
        }
#pragma unroll
        for (int o = 16; o > 0; o >>= 1)
            il += __shfl_down_sync(0xffffffffu, il, o);
        if (lane == 0) atomicAdd(&g_inter_sum, il);
    }
}

// ---------------- per-row combine: 157 partials + margin target ----------------
__global__ __launch_bounds__(256) void k_rows(const float* __restrict__ logits,
                                              const int* __restrict__ y) {
    int b = blockIdx.x;
    int tid = threadIdx.x;
    __shared__ float smx[256];
    __shared__ float ssm[256];
    __shared__ int   sbi[256];
    __shared__ float sM, sOut;

    float m = -3.0e38f, s = 0.0f;
    int idx = 0x7fffffff;
    if (tid < NTL) {
        m = g_pmax[b * NTL + tid];
        s = g_psum[b * NTL + tid];
        idx = g_pbi[b * NTL + tid];
    }
    smx[tid] = m; sbi[tid] = idx;
    __syncthreads();
    for (int o = 128; o > 0; o >>= 1) {
        if (tid < o) {
            float v2 = smx[tid + o]; int i2 = sbi[tid + o];
            if (v2 > smx[tid] || (v2 == smx[tid] && i2 < sbi[tid])) {
                smx[tid] = v2; sbi[tid] = i2;
            }
        }
        __syncthreads();
    }
    float M0 = smx[0];
    int amax = sbi[0];
    int tgt = y[b];

    if (tid == 0) {
        float xl = g_xlen[b];
        float cs_t = logits[(size_t)b * CLS + tgt];
        float ct = cs_t / xl;
        float c2 = ct * ct;
        float cosm = 8.0f * c2 * c2 - 8.0f * c2 + 1.0f;
        const float PI_F = 3.14159265f;
        float theta = acosf(ct);
        float kk = floorf(4.0f * theta / PI_F);
        float sign = 1.0f - 2.0f * fmodf(kk, 2.0f);
        float phi = sign * cosm - 2.0f * kk;
        const float LAMB = 1500.0f / 1.1f;
        const float FCO = 1.0f / (1.0f + LAMB);
        float out_t = cs_t + FCO * (phi * xl - cs_t);
        sOut = out_t;
        sM = fmaxf(M0, out_t);
    }
    __syncthreads();
    float M = sM;
    ssm[tid] = s * __expf(m - M);
    __syncthreads();
    for (int o = 128; o > 0; o >>= 1) {
        if (tid < o) ssm[tid] += ssm[tid + o];
        __syncthreads();
    }
    if (tid == 0) {
        float out_t = sOut;
        float cs_t = logits[(size_t)b * CLS + tgt];
        float sum = ssm[0] + __expf(out_t - M) - __expf(cs_t - M);
        float lse = logf(sum);
        g_row_ce[b] = -(out_t - M - lse);
        g_row_correct[b] = (amax == tgt) ? 1 : 0;
    }
}

__global__ __launch_bounds__(256) void k_final(float* __restrict__ out) {
    __shared__ float s[256];
    __shared__ int   c[256];
    int tid = threadIdx.x;
    s[tid] = g_row_ce[tid];
    c[tid] = g_row_correct[tid];
    __syncthreads();
    for (int o = 128; o > 0; o >>= 1) {
        if (tid < o) { s[tid] += s[tid + o]; c[tid] += c[tid + o]; }
        __syncthreads();
    }
    if (tid == 0) {
        float ce = s[0] / (float)BB;
        float inter = g_inter_sum / ((float)BB * (float)(CLS - 1));
        out[0] = ce + 0.01f * inter;
        out[1 + BB * CLS] = (float)c[0] / (float)BB;
        out[2 + BB * CLS] = inter;
    }
}

// ---------------- launch ----------------
extern "C" void kernel_launch(void* const* d_in, const int* in_sizes, int n_in,
                              void* d_out, int out_size) {
    const float* emb = (const float*)d_in[0];
    const int*   y   = (const int*)d_in[1];
    const float* W   = (const float*)d_in[2];
    float* out = (float*)d_out;
    float* logits = out + 1;

    const int DSM = 3 * STG;   // 144KB pipeline; 128x129 f32 epi tile overlays
    cudaFuncSetAttribute(k_gemm, cudaFuncAttributeMaxDynamicSharedMemorySize, DSM);

    dim3 gcn((CLS + 255) / 256, 8);
    k_colnorm<<<gcn, 256>>>(W);
    k_nred<<<(CLS + 255) / 256, 256>>>();
    k_prep<<<2 * BB, 128>>>(emb, W, y);
    dim3 grid(NTL, (2 * BB) / MT);   // 157 x 4
    k_gemm<<<grid, 512, DSM>>>(W, y, logits);
    k_rows<<<BB, 256>>>(logits, y);
    k_final<<<1, 256>>>(out);
}

// round 9
// speedup vs baseline: 1.8388x; 1.8388x over previous
#include <cuda_runtime.h>
#include <cuda_fp16.h>
#include <math.h>
#include <stdint.h>

#define BB   256
#define EMB  512
#define CLS  20000
#define NTL  157              // N tiles

#define MT   128
#define NT   128
#define KC   64
#define NCH  (EMB / KC)       // 8 k-chunks
#define STG  32768            // stage bytes: A 16K | B 16K

// ---------------- device scratch ----------------
__device__ __align__(16) __half g_Bh[(size_t)EMB * CLS];   // normalized W, fp16
__device__ __align__(16) __half g_Ah[2 * BB * EMB];        // [emb; Wy] fp16
__device__ float g_n2p[8 * CLS];
__device__ float g_inv[CLS];
__device__ float g_xlen[BB];
__device__ float g_pmax[BB * NTL];
__device__ float g_psum[BB * NTL];
__device__ int   g_pbi [BB * NTL];
__device__ float g_inter_sum;
__device__ float g_row_ce[BB];
__device__ int   g_row_correct[BB];

// ---------------- PTX helpers ----------------
__device__ __forceinline__ uint32_t s2u(const void* p) {
    return (uint32_t)__cvta_generic_to_shared(p);
}
__device__ __forceinline__ void cp_async16(uint32_t dst, const void* src, int szbytes) {
    asm volatile("cp.async.cg.shared.global [%0], [%1], 16, %2;"
                 :: "r"(dst), "l"(src), "r"(szbytes));
}
#define CP_COMMIT() asm volatile("cp.async.commit_group;" ::: "memory")
#define CP_WAIT(n)  asm volatile("cp.async.wait_group %0;" :: "n"(n) : "memory")

__device__ __forceinline__ void ldm_x4(uint32_t* r, uint32_t addr) {
    asm volatile("ldmatrix.sync.aligned.m8n8.x4.shared.b16 {%0,%1,%2,%3}, [%4];"
                 : "=r"(r[0]), "=r"(r[1]), "=r"(r[2]), "=r"(r[3]) : "r"(addr));
}
__device__ __forceinline__ void ldm_x4_t(uint32_t* r, uint32_t addr) {
    asm volatile("ldmatrix.sync.aligned.m8n8.x4.trans.shared.b16 {%0,%1,%2,%3}, [%4];"
                 : "=r"(r[0]), "=r"(r[1]), "=r"(r[2]), "=r"(r[3]) : "r"(addr));
}
__device__ __forceinline__ void mma16816(float* c, const uint32_t* a,
                                         uint32_t b0, uint32_t b1) {
    asm volatile("mma.sync.aligned.m16n8k16.row.col.f32.f16.f16.f32 "
                 "{%0,%1,%2,%3}, {%4,%5,%6,%7}, {%8,%9}, {%0,%1,%2,%3};"
                 : "+f"(c[0]), "+f"(c[1]), "+f"(c[2]), "+f"(c[3])
                 : "r"(a[0]), "r"(a[1]), "r"(a[2]), "r"(a[3]), "r"(b0), "r"(b1));
}

// ---------------- colnorm partials ----------------
__global__ void k_colnorm(const float* __restrict__ W) {
    int j = blockIdx.x * blockDim.x + threadIdx.x;
    if (blockIdx.x == 0 && blockIdx.y == 0 && threadIdx.x == 0) g_inter_sum = 0.0f;
    if (j >= CLS) return;
    int i0 = blockIdx.y * 64;
    float s = 0.0f;
#pragma unroll 8
    for (int i = 0; i < 64; i++) {
        float v = W[(size_t)(i0 + i) * CLS + j];
        s += v * v;
    }
    g_n2p[blockIdx.y * CLS + j] = s;
}

__global__ void k_nred() {
    int j = blockIdx.x * blockDim.x + threadIdx.x;
    if (j >= CLS) return;
    float s = 0.0f;
#pragma unroll
    for (int p = 0; p < 8; p++) s += g_n2p[p * CLS + j];
    g_inv[j] = rsqrtf(s);
}

// ---------------- normalize W -> fp16 (streaming, off critical path) ----------------
__global__ void k_whalf(const float* __restrict__ W) {
    int i = blockIdx.y;
    int j0 = blockIdx.x * 2048 + threadIdx.x * 8;
    if (j0 >= CLS) return;
    size_t base = (size_t)i * CLS + j0;
    float4 v0 = *(const float4*)(W + base);
    float4 v1 = *(const float4*)(W + base + 4);
    float f[8] = {v0.x, v0.y, v0.z, v0.w, v1.x, v1.y, v1.z, v1.w};
    alignas(16) __half hb[8];
#pragma unroll
    for (int q = 0; q < 8; q++)
        hb[q] = __float2half_rn(f[q] * g_inv[j0 + q]);
    *(uint4*)(g_Bh + base) = *(const uint4*)hb;
}

// 512 blocks: b<BB: emb fp16 + xlen; else Wy gather (already fp16)
__global__ void k_prep(const float* __restrict__ emb,
                       const int* __restrict__ y) {
    int b = blockIdx.x;
    int tid = threadIdx.x;   // 128
    if (b < BB) {
        float s = 0.0f;
        for (int k = tid; k < EMB; k += 128) {
            float v = emb[b * EMB + k];
            s += v * v;
            g_Ah[b * EMB + k] = __float2half_rn(v);
        }
        __shared__ float sm[128];
        sm[tid] = s;
        __syncthreads();
        for (int o = 64; o > 0; o >>= 1) {
            if (tid < o) sm[tid] += sm[tid + o];
            __syncthreads();
        }
        if (tid == 0) g_xlen[b] = sqrtf(sm[0]);
    } else {
        int t = y[b - BB];
        for (int k = tid; k < EMB; k += 128)
            g_Ah[b * EMB + k] = g_Bh[(size_t)k * CLS + t];
    }
}

// ---------------- single-product fp16 GEMM, 256 thr, 2 CTAs/SM ----------------
__global__ __launch_bounds__(256, 2) void k_gemm(const int* __restrict__ y,
                                                 float* __restrict__ logits) {
    extern __shared__ __align__(16) char dsm[];
    __shared__ float spm[256];
    __shared__ float sse[256];
    __shared__ int   sbx[256];
    uint32_t sb = s2u(dsm);

    int tid  = threadIdx.x;
    int wid  = tid >> 5, lane = tid & 31;
    int wm   = wid & 3, wn = wid >> 2;    // warp tile 32 (M) x 64 (N)
    int bn   = blockIdx.x, bm = blockIdx.y;
    int rowBase = bm * MT, colBase = bn * NT;

    float acc[2][8][4];
#pragma unroll
    for (int mi = 0; mi < 2; mi++)
#pragma unroll
        for (int ni = 0; ni < 8; ni++)
#pragma unroll
            for (int k = 0; k < 4; k++) acc[mi][ni][k] = 0.0f;

    // A: 128x64 fp16 (128B rows, swz c8^(r&7)); B: 64x128 fp16 (256B rows, swz c16^(r&7))
    auto load_tiles = [&](int kc, int s) {
        uint32_t base = sb + s * STG;
#pragma unroll
        for (int i = 0; i < 4; i++) {
            int id = i * 256 + tid;
            int r = id >> 3, c8 = id & 7;
            uint32_t soff = (uint32_t)(r * 128 + ((c8 ^ (r & 7)) << 4));
            cp_async16(base + soff, g_Ah + (size_t)(rowBase + r) * EMB + kc + c8 * 8, 16);
        }
#pragma unroll
        for (int i = 0; i < 4; i++) {
            int id = i * 256 + tid;
            int r = id >> 4, c16 = id & 15;
            int col = colBase + c16 * 8;
            int ok = (col < CLS) ? 16 : 0;
            uint32_t soff = (uint32_t)(r * 256 + ((c16 ^ (r & 7)) << 4));
            cp_async16(base + 16384 + soff,
                       g_Bh + (size_t)(kc + r) * CLS + (ok ? col : colBase), ok);
        }
    };

    load_tiles(0, 0); CP_COMMIT();
    load_tiles(KC, 1); CP_COMMIT();

    int ln15 = lane & 15, half = lane >> 4;

    for (int ch = 0; ch < NCH; ch++) {
        if (ch + 1 < NCH) { CP_WAIT(1); } else { CP_WAIT(0); }
        __syncthreads();
        uint32_t base = sb + (ch & 1) * STG;
#pragma unroll
        for (int ks = 0; ks < 4; ks++) {
            uint32_t ah[2][4], bf[4][4];
#pragma unroll
            for (int mi = 0; mi < 2; mi++) {
                int r = wm * 32 + mi * 16 + ln15;
                int c8 = ks * 2 + half;
                uint32_t off = (uint32_t)(r * 128 + ((c8 ^ (r & 7)) << 4));
                ldm_x4(ah[mi], base + off);
            }
#pragma unroll
            for (int nb = 0; nb < 4; nb++) {
                int r = ks * 16 + ln15;
                int c16 = wn * 8 + nb * 2 + half;
                uint32_t off = (uint32_t)(r * 256 + ((c16 ^ (r & 7)) << 4));
                ldm_x4_t(bf[nb], base + 16384 + off);
            }
#pragma unroll
            for (int mi = 0; mi < 2; mi++)
#pragma unroll
                for (int ni = 0; ni < 8; ni++)
                    mma16816(acc[mi][ni], ah[mi],
                             bf[ni >> 1][(ni & 1) * 2], bf[ni >> 1][(ni & 1) * 2 + 1]);
        }
        __syncthreads();
        if (ch + 2 < NCH) { load_tiles((ch + 2) * KC, ch & 1); CP_COMMIT(); }
    }

    // ---------------- epilogue ----------------
    if (bm < 2) {
        float* epi = (float*)dsm;   // [128][129] raw acc
#pragma unroll
        for (int mi = 0; mi < 2; mi++)
#pragma unroll
            for (int ni = 0; ni < 8; ni++)
#pragma unroll
                for (int k = 0; k < 4; k++) {
                    int row = wm * 32 + mi * 16 + (k >> 1) * 8 + (lane >> 2);
                    int col = wn * 64 + ni * 8 + (lane & 3) * 2 + (k & 1);
                    epi[row * 129 + col] = acc[mi][ni][k];
                }
        __syncthreads();
        // coalesced logits store
        {
            int r0 = tid >> 7, c0 = tid & 127;
            int j = colBase + c0;
            if (j < CLS) {
#pragma unroll 8
                for (int rr = 0; rr < 64; rr++) {
                    int mm = rr * 2 + r0;
                    int b = rowBase + mm;
                    float xl = g_xlen[b];
                    float v = epi[mm * 129 + c0];
                    float cv = fminf(fmaxf(v / xl, -1.0f), 1.0f);
                    logits[(size_t)b * CLS + j] = cv * xl;
                }
            }
        }
        // per-(row, 64-col-half) softmax/argmax partials
        {
            int row = tid & 127, q = tid >> 7;
            float xl = g_xlen[rowBase + row];
            float bv = -3.0e38f, se = 0.0f;
            int bi = 0x7fffffff;
#pragma unroll 8
            for (int c = 0; c < 64; c++) {
                int j = colBase + q * 64 + c;
                if (j < CLS) {
                    float v = epi[row * 129 + q * 64 + c];
                    float cv = fminf(fmaxf(v / xl, -1.0f), 1.0f) * xl;
                    if (cv > bv) { bv = cv; bi = j; }
                }
            }
#pragma unroll 8
            for (int c = 0; c < 64; c++) {
                int j = colBase + q * 64 + c;
                if (j < CLS) {
                    float v = epi[row * 129 + q * 64 + c];
                    float cv = fminf(fmaxf(v / xl, -1.0f), 1.0f) * xl;
                    se += __expf(cv - bv);
                }
            }
            spm[q * 128 + row] = bv;
            sse[q * 128 + row] = se;
            sbx[q * 128 + row] = bi;
        }
        __syncthreads();
        if (tid < 128) {
            float M = -3.0e38f, sum = 0.0f;
            int bi = 0x7fffffff;
#pragma unroll
            for (int q = 0; q < 2; q++) {
                float m = spm[q * 128 + tid];
                if (m > M) { M = m; bi = sbx[q * 128 + tid]; }
            }
#pragma unroll
            for (int q = 0; q < 2; q++)
                sum += sse[q * 128 + tid] * __expf(spm[q * 128 + tid] - M);
            int b = rowBase + tid;
            g_pmax[b * NTL + bn] = M;
            g_psum[b * NTL + bn] = sum;
            g_pbi [b * NTL + bn] = bi;
        }
    } else {
        float il = 0.0f;
#pragma unroll
        for (int mi = 0; mi < 2; mi++) {
#pragma unroll
            for (int k2 = 0; k2 < 2; k2++) {
                int row = wm * 32 + mi * 16 + k2 * 8 + (lane >> 2);
                int b = rowBase + row - BB;
                int t = y[b];
#pragma unroll
                for (int ni = 0; ni < 8; ni++)
#pragma unroll
                    for (int p = 0; p < 2; p++) {
                        int j = colBase + wn * 64 + ni * 8 + (lane & 3) * 2 + p;
                        if (j < CLS && j != t) {
                            float c = acc[mi][ni][k2 * 2 + p];
                            float d2 = fmaxf(2.0f - 2.0f * c, 0.0f);
                            il += 1.0f / d2;
                        }
                    }
            }
        }
#pragma unroll
        for (int o = 16; o > 0; o >>= 1)
            il += __shfl_down_sync(0xffffffffu, il, o);
        if (lane == 0) atomicAdd(&g_inter_sum, il);
    }
}

// ---------------- per-row combine: 157 partials + margin target ----------------
__global__ __launch_bounds__(256) void k_rows(const float* __restrict__ logits,
                                              const int* __restrict__ y) {
    int b = blockIdx.x;
    int tid = threadIdx.x;
    __shared__ float smx[256];
    __shared__ float ssm[256];
    __shared__ int   sbi[256];
    __shared__ float sM, sOut;

    float m = -3.0e38f, s = 0.0f;
    int idx = 0x7fffffff;
    if (tid < NTL) {
        m = g_pmax[b * NTL + tid];
        s = g_psum[b * NTL + tid];
        idx = g_pbi[b * NTL + tid];
    }
    smx[tid] = m; sbi[tid] = idx;
    __syncthreads();
    for (int o = 128; o > 0; o >>= 1) {
        if (tid < o) {
            float v2 = smx[tid + o]; int i2 = sbi[tid + o];
            if (v2 > smx[tid] || (v2 == smx[tid] && i2 < sbi[tid])) {
                smx[tid] = v2; sbi[tid] = i2;
            }
        }
        __syncthreads();
    }
    float M0 = smx[0];
    int amax = sbi[0];
    int tgt = y[b];

    if (tid == 0) {
        float xl = g_xlen[b];
        float cs_t = logits[(size_t)b * CLS + tgt];
        float ct = cs_t / xl;
        float c2 = ct * ct;
        float cosm = 8.0f * c2 * c2 - 8.0f * c2 + 1.0f;
        const float PI_F = 3.14159265f;
        float theta = acosf(ct);
        float kk = floorf(4.0f * theta / PI_F);
        float sign = 1.0f - 2.0f * fmodf(kk, 2.0f);
        float phi = sign * cosm - 2.0f * kk;
        const float LAMB = 1500.0f / 1.1f;
        const float FCO = 1.0f / (1.0f + LAMB);
        float out_t = cs_t + FCO * (phi * xl - cs_t);
        sOut = out_t;
        sM = fmaxf(M0, out_t);
    }
    __syncthreads();
    float M = sM;
    ssm[tid] = s * __expf(m - M);
    __syncthreads();
    for (int o = 128; o > 0; o >>= 1) {
        if (tid < o) ssm[tid] += ssm[tid + o];
        __syncthreads();
    }
    if (tid == 0) {
        float out_t = sOut;
        float cs_t = logits[(size_t)b * CLS + tgt];
        float sum = ssm[0] + __expf(out_t - M) - __expf(cs_t - M);
        float lse = logf(sum);
        g_row_ce[b] = -(out_t - M - lse);
        g_row_correct[b] = (amax == tgt) ? 1 : 0;
    }
}

__global__ __launch_bounds__(256) void k_final(float* __restrict__ out) {
    __shared__ float s[256];
    __shared__ int   c[256];
    int tid = threadIdx.x;
    s[tid] = g_row_ce[tid];
    c[tid] = g_row_correct[tid];
    __syncthreads();
    for (int o = 128; o > 0; o >>= 1) {
        if (tid < o) { s[tid] += s[tid + o]; c[tid] += c[tid + o]; }
        __syncthreads();
    }
    if (tid == 0) {
        float ce = s[0] / (float)BB;
        float inter = g_inter_sum / ((float)BB * (float)(CLS - 1));
        out[0] = ce + 0.01f * inter;
        out[1 + BB * CLS] = (float)c[0] / (float)BB;
        out[2 + BB * CLS] = inter;
    }
}

// ---------------- launch ----------------
extern "C" void kernel_launch(void* const* d_in, const int* in_sizes, int n_in,
                              void* d_out, int out_size) {
    const float* emb = (const float*)d_in[0];
    const int*   y   = (const int*)d_in[1];
    const float* W   = (const float*)d_in[2];
    float* out = (float*)d_out;
    float* logits = out + 1;

    const int DSM = 66048;   // max(2x32KB stages, 128x129 f32 epi tile)
    cudaFuncSetAttribute(k_gemm, cudaFuncAttributeMaxDynamicSharedMemorySize, DSM);

    dim3 gcn((CLS + 255) / 256, 8);
    k_colnorm<<<gcn, 256>>>(W);
    k_nred<<<(CLS + 255) / 256, 256>>>();
    dim3 gwh((CLS + 2047) / 2048, EMB);
    k_whalf<<<gwh, 256>>>(W);
    k_prep<<<2 * BB, 128>>>(emb, y);
    dim3 grid(NTL, (2 * BB) / MT);   // 157 x 4
    k_gemm<<<grid, 256, DSM>>>(y, logits);
    k_rows<<<BB, 256>>>(logits, y);
    k_final<<<1, 256>>>(out);
}

// round 10
// speedup vs baseline: 1.9146x; 1.0412x over previous
#include <cuda_runtime.h>
#include <cuda_fp16.h>
#include <math.h>
#include <stdint.h>

#define BB   256
#define EMB  512
#define CLS  20000
#define NTL  157              // N tiles

#define MT   128
#define NT   128
#define KC   64
#define NCH  (EMB / KC)       // 8 k-chunks
#define STG  32768            // stage bytes: A 16K | B 16K

// ---------------- device scratch ----------------
__device__ __align__(16) __half g_Bh[(size_t)EMB * CLS];   // raw W, fp16
__device__ __align__(16) __half g_Ah[2 * BB * EMB];        // [emb; Wy_norm] fp16
__device__ float g_n2p[8 * CLS];
__device__ float g_inv[CLS];
__device__ float g_xlen[BB];
__device__ float g_pmax[BB * NTL];
__device__ float g_psum[BB * NTL];
__device__ int   g_pbi [BB * NTL];
__device__ float g_inter_sum;
__device__ float g_row_ce[BB];
__device__ int   g_row_correct[BB];

// ---------------- PTX helpers ----------------
__device__ __forceinline__ uint32_t s2u(const void* p) {
    return (uint32_t)__cvta_generic_to_shared(p);
}
__device__ __forceinline__ void cp_async16(uint32_t dst, const void* src, int szbytes) {
    asm volatile("cp.async.cg.shared.global [%0], [%1], 16, %2;"
                 :: "r"(dst), "l"(src), "r"(szbytes));
}
#define CP_COMMIT() asm volatile("cp.async.commit_group;" ::: "memory")
#define CP_WAIT(n)  asm volatile("cp.async.wait_group %0;" :: "n"(n) : "memory")

__device__ __forceinline__ void ldm_x4(uint32_t* r, uint32_t addr) {
    asm volatile("ldmatrix.sync.aligned.m8n8.x4.shared.b16 {%0,%1,%2,%3}, [%4];"
                 : "=r"(r[0]), "=r"(r[1]), "=r"(r[2]), "=r"(r[3]) : "r"(addr));
}
__device__ __forceinline__ void ldm_x4_t(uint32_t* r, uint32_t addr) {
    asm volatile("ldmatrix.sync.aligned.m8n8.x4.trans.shared.b16 {%0,%1,%2,%3}, [%4];"
                 : "=r"(r[0]), "=r"(r[1]), "=r"(r[2]), "=r"(r[3]) : "r"(addr));
}
__device__ __forceinline__ void mma16816(float* c, const uint32_t* a,
                                         uint32_t b0, uint32_t b1) {
    asm volatile("mma.sync.aligned.m16n8k16.row.col.f32.f16.f16.f32 "
                 "{%0,%1,%2,%3}, {%4,%5,%6,%7}, {%8,%9}, {%0,%1,%2,%3};"
                 : "+f"(c[0]), "+f"(c[1]), "+f"(c[2]), "+f"(c[3])
                 : "r"(a[0]), "r"(a[1]), "r"(a[2]), "r"(a[3]), "r"(b0), "r"(b1));
}

// ---------------- fused: W cast fp16 + column-norm partials (single 41MB pass) ----------------
__global__ void k_wprep(const float* __restrict__ W) {
    int j = blockIdx.x * blockDim.x + threadIdx.x;
    if (j >= CLS) return;
    int i0 = blockIdx.y * 64;
    float s = 0.0f;
#pragma unroll 8
    for (int i = 0; i < 64; i++) {
        size_t o = (size_t)(i0 + i) * CLS + j;
        float v = W[o];
        s += v * v;
        g_Bh[o] = __float2half_rn(v);
    }
    g_n2p[blockIdx.y * CLS + j] = s;
}

__global__ void k_nred() {
    int j = blockIdx.x * blockDim.x + threadIdx.x;
    if (blockIdx.x == 0 && threadIdx.x == 0) g_inter_sum = 0.0f;
    if (j >= CLS) return;
    float s = 0.0f;
#pragma unroll
    for (int p = 0; p < 8; p++) s += g_n2p[p * CLS + j];
    g_inv[j] = rsqrtf(s);
}

// 512 blocks: b<BB: emb fp16 + xlen; else Wy = W[:,t]*inv[t] fp16
__global__ void k_prep(const float* __restrict__ emb,
                       const float* __restrict__ W,
                       const int* __restrict__ y) {
    int b = blockIdx.x;
    int tid = threadIdx.x;   // 128
    if (b < BB) {
        float s = 0.0f;
        for (int k = tid; k < EMB; k += 128) {
            float v = emb[b * EMB + k];
            s += v * v;
            g_Ah[b * EMB + k] = __float2half_rn(v);
        }
        __shared__ float sm[128];
        sm[tid] = s;
        __syncthreads();
        for (int o = 64; o > 0; o >>= 1) {
            if (tid < o) sm[tid] += sm[tid + o];
            __syncthreads();
        }
        if (tid == 0) g_xlen[b] = sqrtf(sm[0]);
    } else {
        int t = y[b - BB];
        float inv = g_inv[t];
        for (int k = tid; k < EMB; k += 128)
            g_Ah[b * EMB + k] = __float2half_rn(W[(size_t)k * CLS + t] * inv);
    }
}

// ---------------- fp16 GEMM: 512 thr, 16 warps, 32x32 warp tile, 1 CTA/SM ----------------
__global__ __launch_bounds__(512, 1) void k_gemm(const int* __restrict__ y,
                                                 float* __restrict__ logits) {
    extern __shared__ __align__(16) char dsm[];
    __shared__ float sInv[128];
    __shared__ float spm[512];
    __shared__ float sse[512];
    __shared__ int   sbx[512];
    uint32_t sb = s2u(dsm);

    int tid  = threadIdx.x;
    int wid  = tid >> 5, lane = tid & 31;
    int wm   = wid & 3, wn = wid >> 2;    // warp tile 32 (M) x 32 (N)
    int bn   = blockIdx.x, bm = blockIdx.y;
    int rowBase = bm * MT, colBase = bn * NT;

    if (tid < 128) {
        int j = colBase + tid;
        sInv[tid] = (j < CLS) ? g_inv[j] : 1.0f;
    }

    float acc[2][4][4];
#pragma unroll
    for (int mi = 0; mi < 2; mi++)
#pragma unroll
        for (int ni = 0; ni < 4; ni++)
#pragma unroll
            for (int k = 0; k < 4; k++) acc[mi][ni][k] = 0.0f;

    // A: 128x64 fp16 (128B rows, swz c8^(r&7)); B: 64x128 fp16 (256B rows, swz c16^(r&7))
    auto load_tiles = [&](int kc, int s) {
        uint32_t base = sb + s * STG;
#pragma unroll
        for (int i = 0; i < 2; i++) {
            int id = i * 512 + tid;
            int r = id >> 3, c8 = id & 7;
            uint32_t soff = (uint32_t)(r * 128 + ((c8 ^ (r & 7)) << 4));
            cp_async16(base + soff, g_Ah + (size_t)(rowBase + r) * EMB + kc + c8 * 8, 16);
        }
#pragma unroll
        for (int i = 0; i < 2; i++) {
            int id = i * 512 + tid;
            int r = id >> 4, c16 = id & 15;
            int col = colBase + c16 * 8;
            int ok = (col < CLS) ? 16 : 0;
            uint32_t soff = (uint32_t)(r * 256 + ((c16 ^ (r & 7)) << 4));
            cp_async16(base + 16384 + soff,
                       g_Bh + (size_t)(kc + r) * CLS + (ok ? col : colBase), ok);
        }
    };

    load_tiles(0, 0); CP_COMMIT();
    load_tiles(KC, 1); CP_COMMIT();

    int ln15 = lane & 15, half = lane >> 4;

    for (int ch = 0; ch < NCH; ch++) {
        if (ch + 1 < NCH) { CP_WAIT(1); } else { CP_WAIT(0); }
        __syncthreads();
        uint32_t base = sb + (ch & 1) * STG;
#pragma unroll
        for (int ks = 0; ks < 4; ks++) {
            uint32_t ah[2][4], bf[2][4];
#pragma unroll
            for (int mi = 0; mi < 2; mi++) {
                int r = wm * 32 + mi * 16 + ln15;
                int c8 = ks * 2 + half;
                uint32_t off = (uint32_t)(r * 128 + ((c8 ^ (r & 7)) << 4));
                ldm_x4(ah[mi], base + off);
            }
#pragma unroll
            for (int nb = 0; nb < 2; nb++) {
                int r = ks * 16 + ln15;
                int c16 = wn * 4 + nb * 2 + half;
                uint32_t off = (uint32_t)(r * 256 + ((c16 ^ (r & 7)) << 4));
                ldm_x4_t(bf[nb], base + 16384 + off);
            }
#pragma unroll
            for (int mi = 0; mi < 2; mi++)
#pragma unroll
                for (int ni = 0; ni < 4; ni++)
                    mma16816(acc[mi][ni], ah[mi],
                             bf[ni >> 1][(ni & 1) * 2], bf[ni >> 1][(ni & 1) * 2 + 1]);
        }
        __syncthreads();
        if (ch + 2 < NCH) { load_tiles((ch + 2) * KC, ch & 1); CP_COMMIT(); }
    }

    // ---------------- epilogue (normalization applied here: cos_raw = acc * inv[j]) ----------------
    if (bm < 2) {
        float* epi = (float*)dsm;   // [128][129] raw acc
#pragma unroll
        for (int mi = 0; mi < 2; mi++)
#pragma unroll
            for (int ni = 0; ni < 4; ni++)
#pragma unroll
                for (int k = 0; k < 4; k++) {
                    int row = wm * 32 + mi * 16 + (k >> 1) * 8 + (lane >> 2);
                    int col = wn * 32 + ni * 8 + (lane & 3) * 2 + (k & 1);
                    epi[row * 129 + col] = acc[mi][ni][k];
                }
        __syncthreads();
        // coalesced logits store
        {
            int r0 = tid >> 7, c0 = tid & 127;   // r0 0..3
            int j = colBase + c0;
            if (j < CLS) {
                float inv = sInv[c0];
#pragma unroll 8
                for (int rr = 0; rr < 32; rr++) {
                    int mm = rr * 4 + r0;
                    int b = rowBase + mm;
                    float xl = g_xlen[b];
                    float v = epi[mm * 129 + c0] * inv;
                    float cv = fminf(fmaxf(v / xl, -1.0f), 1.0f);
                    logits[(size_t)b * CLS + j] = cv * xl;
                }
            }
        }
        // per-(row, 32-col quarter) softmax/argmax partials
        {
            int row = tid & 127, q = tid >> 7;
            float xl = g_xlen[rowBase + row];
            int cb = q * 32;
            bool valid = (colBase + cb) < CLS;
            float bv = -3.0e38f, se = 0.0f;
            int bi = 0x7fffffff;
            if (valid) {
#pragma unroll 8
                for (int c = 0; c < 32; c++) {
                    float v = epi[row * 129 + cb + c] * sInv[cb + c];
                    float cv = fminf(fmaxf(v / xl, -1.0f), 1.0f) * xl;
                    if (cv > bv) { bv = cv; bi = colBase + cb + c; }
                }
#pragma unroll 8
                for (int c = 0; c < 32; c++) {
                    float v = epi[row * 129 + cb + c] * sInv[cb + c];
                    float cv = fminf(fmaxf(v / xl, -1.0f), 1.0f) * xl;
                    se += __expf(cv - bv);
                }
            }
            spm[q * 128 + row] = bv;
            sse[q * 128 + row] = se;
            sbx[q * 128 + row] = bi;
        }
        __syncthreads();
        if (tid < 128) {
            float M = -3.0e38f, sum = 0.0f;
            int bi = 0x7fffffff;
#pragma unroll
            for (int q = 0; q < 4; q++) {
                float m = spm[q * 128 + tid];
                if (m > M) { M = m; bi = sbx[q * 128 + tid]; }
            }
#pragma unroll
            for (int q = 0; q < 4; q++)
                sum += sse[q * 128 + tid] * __expf(spm[q * 128 + tid] - M);
            int b = rowBase + tid;
            g_pmax[b * NTL + bn] = M;
            g_psum[b * NTL + bn] = sum;
            g_pbi [b * NTL + bn] = bi;
        }
    } else {
        float il = 0.0f;
#pragma unroll
        for (int mi = 0; mi < 2; mi++) {
#pragma unroll
            for (int k2 = 0; k2 < 2; k2++) {
                int row = wm * 32 + mi * 16 + k2 * 8 + (lane >> 2);
                int b = rowBase + row - BB;
                int t = y[b];
#pragma unroll
                for (int ni = 0; ni < 4; ni++)
#pragma unroll
                    for (int p = 0; p < 2; p++) {
                        int lc = wn * 32 + ni * 8 + (lane & 3) * 2 + p;
                        int j = colBase + lc;
                        if (j < CLS && j != t) {
                            float c = acc[mi][ni][k2 * 2 + p] * sInv[lc];
                            float d2 = fmaxf(2.0f - 2.0f * c, 0.0f);
                            il += 1.0f / d2;
                        }
                    }
            }
        }
#pragma unroll
        for (int o = 16; o > 0; o >>= 1)
            il += __shfl_down_sync(0xffffffffu, il, o);
        if (lane == 0) atomicAdd(&g_inter_sum, il);
    }
}

// ---------------- per-row combine: 157 partials + margin target ----------------
__global__ __launch_bounds__(256) void k_rows(const float* __restrict__ logits,
                                              const int* __restrict__ y) {
    int b = blockIdx.x;
    int tid = threadIdx.x;
    __shared__ float smx[256];
    __shared__ float ssm[256];
    __shared__ int   sbi[256];
    __shared__ float sM, sOut;

    float m = -3.0e38f, s = 0.0f;
    int idx = 0x7fffffff;
    if (tid < NTL) {
        m = g_pmax[b * NTL + tid];
        s = g_psum[b * NTL + tid];
        idx = g_pbi[b * NTL + tid];
    }
    smx[tid] = m; sbi[tid] = idx;
    __syncthreads();
    for (int o = 128; o > 0; o >>= 1) {
        if (tid < o) {
            float v2 = smx[tid + o]; int i2 = sbi[tid + o];
            if (v2 > smx[tid] || (v2 == smx[tid] && i2 < sbi[tid])) {
                smx[tid] = v2; sbi[tid] = i2;
            }
        }
        __syncthreads();
    }
    float M0 = smx[0];
    int amax = sbi[0];
    int tgt = y[b];

    if (tid == 0) {
        float xl = g_xlen[b];
        float cs_t = logits[(size_t)b * CLS + tgt];
        float ct = cs_t / xl;
        float c2 = ct * ct;
        float cosm = 8.0f * c2 * c2 - 8.0f * c2 + 1.0f;
        const float PI_F = 3.14159265f;
        float theta = acosf(ct);
        float kk = floorf(4.0f * theta / PI_F);
        float sign = 1.0f - 2.0f * fmodf(kk, 2.0f);
        float phi = sign * cosm - 2.0f * kk;
        const float LAMB = 1500.0f / 1.1f;
        const float FCO = 1.0f / (1.0f + LAMB);
        float out_t = cs_t + FCO * (phi * xl - cs_t);
        sOut = out_t;
        sM = fmaxf(M0, out_t);
    }
    __syncthreads();
    float M = sM;
    ssm[tid] = s * __expf(m - M);
    __syncthreads();
    for (int o = 128; o > 0; o >>= 1) {
        if (tid < o) ssm[tid] += ssm[tid + o];
        __syncthreads();
    }
    if (tid == 0) {
        float out_t = sOut;
        float cs_t = logits[(size_t)b * CLS + tgt];
        float sum = ssm[0] + __expf(out_t - M) - __expf(cs_t - M);
        float lse = logf(sum);
        g_row_ce[b] = -(out_t - M - lse);
        g_row_correct[b] = (amax == tgt) ? 1 : 0;
    }
}

__global__ __launch_bounds__(256) void k_final(float* __restrict__ out) {
    __shared__ float s[256];
    __shared__ int   c[256];
    int tid = threadIdx.x;
    s[tid] = g_row_ce[tid];
    c[tid] = g_row_correct[tid];
    __syncthreads();
    for (int o = 128; o > 0; o >>= 1) {
        if (tid < o) { s[tid] += s[tid + o]; c[tid] += c[tid + o]; }
        __syncthreads();
    }
    if (tid == 0) {
        float ce = s[0] / (float)BB;
        float inter = g_inter_sum / ((float)BB * (float)(CLS - 1));
        out[0] = ce + 0.01f * inter;
        out[1 + BB * CLS] = (float)c[0] / (float)BB;
        out[2 + BB * CLS] = inter;
    }
}

// ---------------- launch ----------------
extern "C" void kernel_launch(void* const* d_in, const int* in_sizes, int n_in,
                              void* d_out, int out_size) {
    const float* emb = (const float*)d_in[0];
    const int*   y   = (const int*)d_in[1];
    const float* W   = (const float*)d_in[2];
    float* out = (float*)d_out;
    float* logits = out + 1;

    const int DSM = 66048;   // max(2x32KB stages, 128x129 f32 epi tile)
    cudaFuncSetAttribute(k_gemm, cudaFuncAttributeMaxDynamicSharedMemorySize, DSM);

    dim3 gwp((CLS + 255) / 256, 8);
    k_wprep<<<gwp, 256>>>(W);
    k_nred<<<(CLS + 255) / 256, 256>>>();
    k_prep<<<2 * BB, 128>>>(emb, W, y);
    dim3 grid(NTL, (2 * BB) / MT);   // 157 x 4
    k_gemm<<<grid, 512, DSM>>>(y, logits);
    k_rows<<<BB, 256>>>(logits, y);
    k_final<<<1, 256>>>(out);
}

// round 11
// speedup vs baseline: 1.9562x; 1.0217x over previous
#include <cuda_runtime.h>
#include <cuda_fp16.h>
#include <math.h>
#include <stdint.h>

#define BB   256
#define EMB  512
#define CLS  20000
#define NTL  157              // N tiles

#define MT   128
#define NT   128
#define KC   64
#define NCH  (EMB / KC)       // 8 k-chunks
#define STG  32768            // stage bytes: A 16K | B 16K

// ---------------- device scratch ----------------
__device__ __align__(16) __half g_Bh[(size_t)EMB * CLS];   // raw W, fp16
__device__ __align__(16) __half g_Ah[2 * BB * EMB];        // [emb; Wy_norm] fp16
__device__ float g_n2p[8 * CLS];
__device__ float g_inv[CLS];
__device__ float g_xlen[BB];
__device__ float g_pmax[BB * NTL];
__device__ float g_psum[BB * NTL];
__device__ int   g_pbi [BB * NTL];
__device__ float g_inter_sum;
__device__ float g_row_ce[BB];
__device__ int   g_row_correct[BB];

// ---------------- PTX helpers ----------------
__device__ __forceinline__ uint32_t s2u(const void* p) {
    return (uint32_t)__cvta_generic_to_shared(p);
}
__device__ __forceinline__ void cp_async16(uint32_t dst, const void* src, int szbytes) {
    asm volatile("cp.async.cg.shared.global [%0], [%1], 16, %2;"
                 :: "r"(dst), "l"(src), "r"(szbytes));
}
#define CP_COMMIT() asm volatile("cp.async.commit_group;" ::: "memory")
#define CP_WAIT(n)  asm volatile("cp.async.wait_group %0;" :: "n"(n) : "memory")

__device__ __forceinline__ void ldm_x4(uint32_t* r, uint32_t addr) {
    asm volatile("ldmatrix.sync.aligned.m8n8.x4.shared.b16 {%0,%1,%2,%3}, [%4];"
                 : "=r"(r[0]), "=r"(r[1]), "=r"(r[2]), "=r"(r[3]) : "r"(addr));
}
__device__ __forceinline__ void ldm_x4_t(uint32_t* r, uint32_t addr) {
    asm volatile("ldmatrix.sync.aligned.m8n8.x4.trans.shared.b16 {%0,%1,%2,%3}, [%4];"
                 : "=r"(r[0]), "=r"(r[1]), "=r"(r[2]), "=r"(r[3]) : "r"(addr));
}
__device__ __forceinline__ void mma16816(float* c, const uint32_t* a,
                                         uint32_t b0, uint32_t b1) {
    asm volatile("mma.sync.aligned.m16n8k16.row.col.f32.f16.f16.f32 "
                 "{%0,%1,%2,%3}, {%4,%5,%6,%7}, {%8,%9}, {%0,%1,%2,%3};"
                 : "+f"(c[0]), "+f"(c[1]), "+f"(c[2]), "+f"(c[3])
                 : "r"(a[0]), "r"(a[1]), "r"(a[2]), "r"(a[3]), "r"(b0), "r"(b1));
}

// ---------------- fused: W cast fp16 + column-norm partials (single 41MB pass) ----------------
__global__ void k_wprep(const float* __restrict__ W) {
    int j = blockIdx.x * blockDim.x + threadIdx.x;
    if (j >= CLS) return;
    int i0 = blockIdx.y * 64;
    float s = 0.0f;
#pragma unroll 8
    for (int i = 0; i < 64; i++) {
        size_t o = (size_t)(i0 + i) * CLS + j;
        float v = W[o];
        s += v * v;
        g_Bh[o] = __float2half_rn(v);
    }
    g_n2p[blockIdx.y * CLS + j] = s;
}

__global__ void k_nred() {
    int j = blockIdx.x * blockDim.x + threadIdx.x;
    if (blockIdx.x == 0 && threadIdx.x == 0) g_inter_sum = 0.0f;
    if (j >= CLS) return;
    float s = 0.0f;
#pragma unroll
    for (int p = 0; p < 8; p++) s += g_n2p[p * CLS + j];
    g_inv[j] = rsqrtf(s);
}

// 512 blocks: b<BB: emb fp16 + xlen; else Wy = W[:,t]*inv[t] fp16
__global__ void k_prep(const float* __restrict__ emb,
                       const float* __restrict__ W,
                       const int* __restrict__ y) {
    int b = blockIdx.x;
    int tid = threadIdx.x;   // 128
    if (b < BB) {
        float s = 0.0f;
        for (int k = tid; k < EMB; k += 128) {
            float v = emb[b * EMB + k];
            s += v * v;
            g_Ah[b * EMB + k] = __float2half_rn(v);
        }
        __shared__ float sm[128];
        sm[tid] = s;
        __syncthreads();
        for (int o = 64; o > 0; o >>= 1) {
            if (tid < o) sm[tid] += sm[tid + o];
            __syncthreads();
        }
        if (tid == 0) g_xlen[b] = sqrtf(sm[0]);
    } else {
        int t = y[b - BB];
        float inv = g_inv[t];
        for (int k = tid; k < EMB; k += 128)
            g_Ah[b * EMB + k] = __float2half_rn(W[(size_t)k * CLS + t] * inv);
    }
}

// ---------------- fp16 GEMM: 256 thr, 8 warps (32x64 tiles), 2 CTAs/SM, 3-stage ring ----------------
__global__ __launch_bounds__(256, 2) void k_gemm(const int* __restrict__ y,
                                                 float* __restrict__ logits) {
    extern __shared__ __align__(16) char dsm[];
    __shared__ float sInv[128];
    __shared__ float spm[256];
    __shared__ float sse[256];
    __shared__ int   sbx[256];
    uint32_t sb = s2u(dsm);

    int tid  = threadIdx.x;
    int wid  = tid >> 5, lane = tid & 31;
    int wm   = wid & 3, wn = wid >> 2;    // warp tile 32 (M) x 64 (N)
    int bm   = blockIdx.x, bn = blockIdx.y;   // transposed grid: heavy/light mixed
    int rowBase = bm * MT, colBase = bn * NT;

    if (tid < 128) {
        int j = colBase + tid;
        sInv[tid] = (j < CLS) ? g_inv[j] : 1.0f;
    }

    float acc[2][8][4];
#pragma unroll
    for (int mi = 0; mi < 2; mi++)
#pragma unroll
        for (int ni = 0; ni < 8; ni++)
#pragma unroll
            for (int k = 0; k < 4; k++) acc[mi][ni][k] = 0.0f;

    // A: 128x64 fp16 (128B rows, swz c8^(r&7)); B: 64x128 fp16 (256B rows, swz c16^(r&7))
    auto load_tiles = [&](int kc, int s) {
        uint32_t base = sb + s * STG;
#pragma unroll
        for (int i = 0; i < 4; i++) {
            int id = i * 256 + tid;
            int r = id >> 3, c8 = id & 7;
            uint32_t soff = (uint32_t)(r * 128 + ((c8 ^ (r & 7)) << 4));
            cp_async16(base + soff, g_Ah + (size_t)(rowBase + r) * EMB + kc + c8 * 8, 16);
        }
#pragma unroll
        for (int i = 0; i < 4; i++) {
            int id = i * 256 + tid;
            int r = id >> 4, c16 = id & 15;
            int col = colBase + c16 * 8;
            int ok = (col < CLS) ? 16 : 0;
            uint32_t soff = (uint32_t)(r * 256 + ((c16 ^ (r & 7)) << 4));
            cp_async16(base + 16384 + soff,
                       g_Bh + (size_t)(kc + r) * CLS + (ok ? col : colBase), ok);
        }
    };

    load_tiles(0, 0); CP_COMMIT();
    load_tiles(KC, 1); CP_COMMIT();

    int ln15 = lane & 15, half = lane >> 4;

    for (int ch = 0; ch < NCH; ch++) {
        if (ch + 1 < NCH) { CP_WAIT(1); } else { CP_WAIT(0); }
        __syncthreads();                       // single barrier per chunk
        if (ch + 2 < NCH) { load_tiles((ch + 2) * KC, (ch + 2) % 3); CP_COMMIT(); }
        uint32_t base = sb + (ch % 3) * STG;
#pragma unroll
        for (int ks = 0; ks < 4; ks++) {
            uint32_t ah[2][4], bf[4][4];
#pragma unroll
            for (int mi = 0; mi < 2; mi++) {
                int r = wm * 32 + mi * 16 + ln15;
                int c8 = ks * 2 + half;
                uint32_t off = (uint32_t)(r * 128 + ((c8 ^ (r & 7)) << 4));
                ldm_x4(ah[mi], base + off);
            }
#pragma unroll
            for (int nb = 0; nb < 4; nb++) {
                int r = ks * 16 + ln15;
                int c16 = wn * 8 + nb * 2 + half;
                uint32_t off = (uint32_t)(r * 256 + ((c16 ^ (r & 7)) << 4));
                ldm_x4_t(bf[nb], base + 16384 + off);
            }
#pragma unroll
            for (int mi = 0; mi < 2; mi++)
#pragma unroll
                for (int ni = 0; ni < 8; ni++)
                    mma16816(acc[mi][ni], ah[mi],
                             bf[ni >> 1][(ni & 1) * 2], bf[ni >> 1][(ni & 1) * 2 + 1]);
        }
    }
    __syncthreads();

    // ---------------- epilogue (normalization applied here: cos_raw = acc * inv[j]) ----------------
    if (bm < 2) {
        float* epi = (float*)dsm;   // [128][129] raw acc
#pragma unroll
        for (int mi = 0; mi < 2; mi++)
#pragma unroll
            for (int ni = 0; ni < 8; ni++)
#pragma unroll
                for (int k = 0; k < 4; k++) {
                    int row = wm * 32 + mi * 16 + (k >> 1) * 8 + (lane >> 2);
                    int col = wn * 64 + ni * 8 + (lane & 3) * 2 + (k & 1);
                    epi[row * 129 + col] = acc[mi][ni][k];
                }
        __syncthreads();
        // coalesced logits store
        {
            int r0 = tid >> 7, c0 = tid & 127;
            int j = colBase + c0;
            if (j < CLS) {
                float inv = sInv[c0];
#pragma unroll 8
                for (int rr = 0; rr < 64; rr++) {
                    int mm = rr * 2 + r0;
                    int b = rowBase + mm;
                    float xl = g_xlen[b];
                    float v = epi[mm * 129 + c0] * inv;
                    float cv = fminf(fmaxf(v / xl, -1.0f), 1.0f);
                    logits[(size_t)b * CLS + j] = cv * xl;
                }
            }
        }
        // per-(row, 64-col-half) softmax/argmax partials
        {
            int row = tid & 127, q = tid >> 7;
            float xl = g_xlen[rowBase + row];
            float bv = -3.0e38f, se = 0.0f;
            int bi = 0x7fffffff;
#pragma unroll 8
            for (int c = 0; c < 64; c++) {
                int lc = q * 64 + c;
                int j = colBase + lc;
                if (j < CLS) {
                    float v = epi[row * 129 + lc] * sInv[lc];
                    float cv = fminf(fmaxf(v / xl, -1.0f), 1.0f) * xl;
                    if (cv > bv) { bv = cv; bi = j; }
                }
            }
#pragma unroll 8
            for (int c = 0; c < 64; c++) {
                int lc = q * 64 + c;
                int j = colBase + lc;
                if (j < CLS) {
                    float v = epi[row * 129 + lc] * sInv[lc];
                    float cv = fminf(fmaxf(v / xl, -1.0f), 1.0f) * xl;
                    se += __expf(cv - bv);
                }
            }
            spm[q * 128 + row] = bv;
            sse[q * 128 + row] = se;
            sbx[q * 128 + row] = bi;
        }
        __syncthreads();
        if (tid < 128) {
            float M = -3.0e38f, sum = 0.0f;
            int bi = 0x7fffffff;
#pragma unroll
            for (int q = 0; q < 2; q++) {
                float m = spm[q * 128 + tid];
                if (m > M) { M = m; bi = sbx[q * 128 + tid]; }
            }
#pragma unroll
            for (int q = 0; q < 2; q++)
                sum += sse[q * 128 + tid] * __expf(spm[q * 128 + tid] - M);
            int b = rowBase + tid;
            g_pmax[b * NTL + bn] = M;
            g_psum[b * NTL + bn] = sum;
            g_pbi [b * NTL + bn] = bi;
        }
    } else {
        float il = 0.0f;
#pragma unroll
        for (int mi = 0; mi < 2; mi++) {
#pragma unroll
            for (int k2 = 0; k2 < 2; k2++) {
                int row = wm * 32 + mi * 16 + k2 * 8 + (lane >> 2);
                int b = rowBase + row - BB;
                int t = y[b];
#pragma unroll
                for (int ni = 0; ni < 8; ni++)
#pragma unroll
                    for (int p = 0; p < 2; p++) {
                        int lc = wn * 64 + ni * 8 + (lane & 3) * 2 + p;
                        int j = colBase + lc;
                        if (j < CLS && j != t) {
                            float c = acc[mi][ni][k2 * 2 + p] * sInv[lc];
                            float d2 = fmaxf(2.0f - 2.0f * c, 0.0f);
                            il += 1.0f / d2;
                        }
                    }
            }
        }
#pragma unroll
        for (int o = 16; o > 0; o >>= 1)
            il += __shfl_down_sync(0xffffffffu, il, o);
        if (lane == 0) atomicAdd(&g_inter_sum, il);
    }
}

// ---------------- per-row combine: 157 partials + margin target ----------------
__global__ __launch_bounds__(256) void k_rows(const float* __restrict__ logits,
                                              const int* __restrict__ y) {
    int b = blockIdx.x;
    int tid = threadIdx.x;
    __shared__ float smx[256];
    __shared__ float ssm[256];
    __shared__ int   sbi[256];
    __shared__ float sM, sOut;

    float m = -3.0e38f, s = 0.0f;
    int idx = 0x7fffffff;
    if (tid < NTL) {
        m = g_pmax[b * NTL + tid];
        s = g_psum[b * NTL + tid];
        idx = g_pbi[b * NTL + tid];
    }
    smx[tid] = m; sbi[tid] = idx;
    __syncthreads();
    for (int o = 128; o > 0; o >>= 1) {
        if (tid < o) {
            float v2 = smx[tid + o]; int i2 = sbi[tid + o];
            if (v2 > smx[tid] || (v2 == smx[tid] && i2 < sbi[tid])) {
                smx[tid] = v2; sbi[tid] = i2;
            }
        }
        __syncthreads();
    }
    float M0 = smx[0];
    int amax = sbi[0];
    int tgt = y[b];

    if (tid == 0) {
        float xl = g_xlen[b];
        float cs_t = logits[(size_t)b * CLS + tgt];
        float ct = cs_t / xl;
        float c2 = ct * ct;
        float cosm = 8.0f * c2 * c2 - 8.0f * c2 + 1.0f;
        const float PI_F = 3.14159265f;
        float theta = acosf(ct);
        float kk = floorf(4.0f * theta / PI_F);
        float sign = 1.0f - 2.0f * fmodf(kk, 2.0f);
        float phi = sign * cosm - 2.0f * kk;
        const float LAMB = 1500.0f / 1.1f;
        const float FCO = 1.0f / (1.0f + LAMB);
        float out_t = cs_t + FCO * (phi * xl - cs_t);
        sOut = out_t;
        sM = fmaxf(M0, out_t);
    }
    __syncthreads();
    float M = sM;
    ssm[tid] = s * __expf(m - M);
    __syncthreads();
    for (int o = 128; o > 0; o >>= 1) {
        if (tid < o) ssm[tid] += ssm[tid + o];
        __syncthreads();
    }
    if (tid == 0) {
        float out_t = sOut;
        float cs_t = logits[(size_t)b * CLS + tgt];
        float sum = ssm[0] + __expf(out_t - M) - __expf(cs_t - M);
        float lse = logf(sum);
        g_row_ce[b] = -(out_t - M - lse);
        g_row_correct[b] = (amax == tgt) ? 1 : 0;
    }
}

__global__ __launch_bounds__(256) void k_final(float* __restrict__ out) {
    __shared__ float s[256];
    __shared__ int   c[256];
    int tid = threadIdx.x;
    s[tid] = g_row_ce[tid];
    c[tid] = g_row_correct[tid];
    __syncthreads();
    for (int o = 128; o > 0; o >>= 1) {
        if (tid < o) { s[tid] += s[tid + o]; c[tid] += c[tid + o]; }
        __syncthreads();
    }
    if (tid == 0) {
        float ce = s[0] / (float)BB;
        float inter = g_inter_sum / ((float)BB * (float)(CLS - 1));
        out[0] = ce + 0.01f * inter;
        out[1 + BB * CLS] = (float)c[0] / (float)BB;
        out[2 + BB * CLS] = inter;
    }
}

// ---------------- launch ----------------
extern "C" void kernel_launch(void* const* d_in, const int* in_sizes, int n_in,
                              void* d_out, int out_size) {
    const float* emb = (const float*)d_in[0];
    const int*   y   = (const int*)d_in[1];
    const float* W   = (const float*)d_in[2];
    float* out = (float*)d_out;
    float* logits = out + 1;

    const int DSM = 3 * STG;   // 96KB: 3-stage ring; 128x129 f32 epi tile (66KB) overlays
    cudaFuncSetAttribute(k_gemm, cudaFuncAttributeMaxDynamicSharedMemorySize, DSM);

    dim3 gwp((CLS + 255) / 256, 8);
    k_wprep<<<gwp, 256>>>(W);
    k_nred<<<(CLS + 255) / 256, 256>>>();
    k_prep<<<2 * BB, 128>>>(emb, W, y);
    dim3 grid((2 * BB) / MT, NTL);   // 4 x 157, bm fastest -> heavy/light epilogues interleave
    k_gemm<<<grid, 256, DSM>>>(y, logits);
    k_rows<<<BB, 256>>>(logits, y);
    k_final<<<1, 256>>>(out);
}